// round 12
// baseline (speedup 1.0000x reference)
#include <cuda_runtime.h>
#include <cuda_fp16.h>
#include <cstdint>
#include <math_constants.h>

// Problem shape (fixed)
static constexpr int Bb = 2, Tt = 2048, Cc = 1024, Hh = 16, Dd = 64;

// Scratch (allocation-free device globals), all fp16 operands
__device__ __align__(256) __half g_qkv[(size_t)Bb * Tt * 3 * Cc];  // 25 MB
__device__ __align__(256) __half g_y[(size_t)Bb * Tt * Cc];        // 8 MB
__device__ __align__(256) __half g_xh[(size_t)Bb * Tt * Cc];       // 8 MB
__device__ __align__(256) __half g_wq[(size_t)3 * Cc * Cc];        // 6 MB
__device__ __align__(256) __half g_wo[(size_t)Cc * Cc];            // 2 MB

// ---------------------------------------------------------------------------
// Helpers
// ---------------------------------------------------------------------------
__device__ __forceinline__ uint32_t smem_u32(const void* p) {
    uint32_t a;
    asm("{ .reg .u64 t; cvta.to.shared.u64 t, %1; cvt.u32.u64 %0, t; }"
        : "=r"(a) : "l"(p));
    return a;
}
// mma.m16n8k16 fp16 -> fp32
__device__ __forceinline__ void mma16(float c[4], const uint32_t a[4],
                                      uint32_t b0, uint32_t b1) {
    asm volatile(
        "mma.sync.aligned.m16n8k16.row.col.f32.f16.f16.f32 "
        "{%0,%1,%2,%3}, {%4,%5,%6,%7}, {%8,%9}, {%0,%1,%2,%3};"
        : "+f"(c[0]), "+f"(c[1]), "+f"(c[2]), "+f"(c[3])
        : "r"(a[0]), "r"(a[1]), "r"(a[2]), "r"(a[3]), "r"(b0), "r"(b1));
}
__device__ __forceinline__ void cpa16(uint32_t dst, const void* src) {
    asm volatile("cp.async.cg.shared.global [%0], [%1], 16;"
                 :: "r"(dst), "l"(src));
}
#define CP_COMMIT() asm volatile("cp.async.commit_group;" ::: "memory")
#define CP_WAIT(n)  asm volatile("cp.async.wait_group %0;" :: "n"(n) : "memory")
#define LDSM4(R0, R1, R2, R3, ADDR)                                          \
    asm volatile("ldmatrix.sync.aligned.m8n8.x4.shared.b16 {%0,%1,%2,%3}, [%4];" \
                 : "=r"(R0), "=r"(R1), "=r"(R2), "=r"(R3) : "r"(ADDR))
#define LDSM4T(R0, R1, R2, R3, ADDR)                                         \
    asm volatile("ldmatrix.sync.aligned.m8n8.x4.trans.shared.b16 {%0,%1,%2,%3}, [%4];" \
                 : "=r"(R0), "=r"(R1), "=r"(R2), "=r"(R3) : "r"(ADDR))

// ---------------------------------------------------------------------------
// Fused fp32 -> fp16 conversion of x, W_qkv, W_out (one launch)
// ---------------------------------------------------------------------------
__global__ void __launch_bounds__(256)
cvt_h3(const float* __restrict__ s0, __half* __restrict__ d0, int n0,
       const float* __restrict__ s1, __half* __restrict__ d1, int n1,
       const float* __restrict__ s2, __half* __restrict__ d2, int n2)
{
    int i = blockIdx.x * 256 + threadIdx.x;
    const float* s;
    __half* d;
    if (i < n0) { s = s0; d = d0; }
    else if (i < n0 + n1) { s = s1; d = d1; i -= n0; }
    else if (i < n0 + n1 + n2) { s = s2; d = d2; i -= n0 + n1; }
    else return;
    float4 v = ((const float4*)s)[i];
    ((__half2*)d)[2 * i]     = __floats2half2_rn(v.x, v.y);
    ((__half2*)d)[2 * i + 1] = __floats2half2_rn(v.z, v.w);
}

// ---------------------------------------------------------------------------
// fp16 GEMM: C[M,N] = A[M,K] @ B[N,K]^T (row-major, K contiguous, fp16 in)
// 128x128 block tile, K-chunks of 64 halves (128B rows). 256 threads,
// 8 warps 2x4, warp tile 64x32. 3-stage cp.async pipeline, 2 CTAs/SM.
// All 6 LDSM of a k16-step hoisted ahead of its 32-MMA run.
// ---------------------------------------------------------------------------
static constexpr int GLD = 72;                  // smem row stride (halves)
static constexpr int GSTG_H = 2 * 128 * GLD;    // halves per stage (A+B)
static constexpr int GSMEM = 3 * GSTG_H * 2;    // 110592 bytes

template <int OUT_HALF>
__global__ void __launch_bounds__(256, 2)
gemm_nt_h(const __half* __restrict__ A, const __half* __restrict__ B,
          void* __restrict__ Cv, int N, int K)
{
    extern __shared__ char smc[];
    const uint32_t sb = smem_u32(smc);
    const int tid = threadIdx.x, warp = tid >> 5, lane = tid & 31;
    const int g = lane >> 2, tig = lane & 3;
    const int bm = blockIdx.y * 128, bn = blockIdx.x * 128;
    const int wm = (warp >> 2) * 64, wn = (warp & 3) * 32;

    // ldmatrix offsets (bytes): row = (lane&15), col-half = (lane>>4)*16B
    const uint32_t a_off =
        ((uint32_t)(wm + (lane & 15)) * GLD + ((lane >> 4) << 3)) * 2;
    const uint32_t b_off = (uint32_t)128 * GLD * 2 +
        ((uint32_t)(wn + (lane & 15)) * GLD + ((lane >> 4) << 3)) * 2;

    float acc[4][4][4];
#pragma unroll
    for (int mt = 0; mt < 4; mt++)
#pragma unroll
        for (int nt = 0; nt < 4; nt++)
#pragma unroll
            for (int q = 0; q < 4; q++) acc[mt][nt][q] = 0.0f;

    auto load_stage = [&](int c, int s) {
        const __half* ga = A + (size_t)bm * K + c * 64;
        const __half* gb = B + (size_t)bn * K + c * 64;
        const uint32_t da = sb + (uint32_t)s * GSTG_H * 2;
        const uint32_t db = da + 128 * GLD * 2;
#pragma unroll
        for (int it = 0; it < 4; it++) {
            int j = tid + it * 256;            // 1024 chunks (128 rows x 8)
            int r = j >> 3, ch = j & 7;
            cpa16(da + (uint32_t)(r * GLD + ch * 8) * 2,
                  ga + (size_t)r * K + ch * 8);
        }
#pragma unroll
        for (int it = 0; it < 4; it++) {
            int j = tid + it * 256;
            int r = j >> 3, ch = j & 7;
            cpa16(db + (uint32_t)(r * GLD + ch * 8) * 2,
                  gb + (size_t)r * K + ch * 8);
        }
        CP_COMMIT();
    };

    const int NCH = K / 64;
    load_stage(0, 0);
    load_stage(1, 1);
#pragma unroll 1
    for (int c = 0; c < NCH; c++) {
        if (c + 2 < NCH) { CP_WAIT(1); } else { CP_WAIT(0); }
        __syncthreads();
        if (c + 2 < NCH) load_stage(c + 2, (c + 2) % 3);
        const uint32_t stg = sb + (uint32_t)(c % 3) * GSTG_H * 2;
        const uint32_t aa = stg + a_off;
        const uint32_t ba = stg + b_off;
#pragma unroll
        for (int ks = 0; ks < 4; ks++) {       // k16 steps within 64
            const uint32_t kb = (uint32_t)(ks * 16) * 2;
            uint32_t af[4][4], bq[2][4];
#pragma unroll
            for (int mt = 0; mt < 4; mt++)
                LDSM4(af[mt][0], af[mt][1], af[mt][2], af[mt][3],
                      aa + (uint32_t)mt * 16 * GLD * 2 + kb);
#pragma unroll
            for (int j = 0; j < 2; j++)
                LDSM4(bq[j][0], bq[j][1], bq[j][2], bq[j][3],
                      ba + (uint32_t)j * 16 * GLD * 2 + kb);
#pragma unroll
            for (int mt = 0; mt < 4; mt++)
#pragma unroll
                for (int j = 0; j < 2; j++) {
                    mma16(acc[mt][2 * j], af[mt], bq[j][0], bq[j][2]);
                    mma16(acc[mt][2 * j + 1], af[mt], bq[j][1], bq[j][3]);
                }
        }
    }

    // Epilogue
#pragma unroll
    for (int mt = 0; mt < 4; mt++) {
        const int row = bm + wm + mt * 16 + g;
#pragma unroll
        for (int nt = 0; nt < 4; nt++) {
            const int col = bn + wn + nt * 8 + 2 * tig;
            if (OUT_HALF) {
                __half* C = (__half*)Cv;
                *(__half2*)(C + (size_t)row * N + col) =
                    __floats2half2_rn(acc[mt][nt][0], acc[mt][nt][1]);
                *(__half2*)(C + (size_t)(row + 8) * N + col) =
                    __floats2half2_rn(acc[mt][nt][2], acc[mt][nt][3]);
            } else {
                float* C = (float*)Cv;
                *(float2*)(C + (size_t)row * N + col) =
                    make_float2(acc[mt][nt][0], acc[mt][nt][1]);
                *(float2*)(C + (size_t)(row + 8) * N + col) =
                    make_float2(acc[mt][nt][2], acc[mt][nt][3]);
            }
        }
    }
}

// ---------------------------------------------------------------------------
// fp16 flash attention: 128 Q rows per CTA, 256 threads (8 warps x 16 rows).
// Register softmax/O. Q/K/P via ldmatrix, V via ldmatrix.trans.
// KV iteration (64-row tiles) unchanged -> bit-identical numerics.
// ---------------------------------------------------------------------------
static constexpr int KLD = 72, VLD = 72, PLD = 72;        // halves
static constexpr int KS_H = 64 * KLD;                     // 4608
static constexpr int VS_H = 64 * VLD;
static constexpr int STG_H = KS_H + VS_H;                 // 9216
static constexpr int PS_OFF_H = 2 * STG_H;                // 18432
static constexpr int FL_SMEM = (PS_OFF_H + 128 * PLD) * 2; // 55296 bytes

__global__ void __launch_bounds__(256)
flash_attn_h(const __half* __restrict__ qkv, __half* __restrict__ y)
{
    extern __shared__ char smc[];
    __half* smh = (__half*)smc;
    const uint32_t sb = smem_u32(smc);
    const int tid = threadIdx.x, warp = tid >> 5, lane = tid & 31;
    const int g = lane >> 2, tig = lane & 3;
    const int q0 = blockIdx.x * 128;
    const int b = blockIdx.y >> 4, h = blockIdx.y & 15;
    const __half* base = qkv + (size_t)b * Tt * 3 * Cc + (size_t)h * Dd;
    __half* Ps = smh + PS_OFF_H;
    const uint32_t ps_base = sb + (uint32_t)PS_OFF_H * 2;

    // ldmatrix offsets (bytes)
    const uint32_t k_off =
        ((uint32_t)(lane & 15) * KLD + ((lane >> 4) << 3)) * 2;
    const uint32_t v_off =
        ((uint32_t)((((lane >> 3) & 1) << 3) + (lane & 7)) * VLD +
         ((lane >> 4) << 3)) * 2;
    const uint32_t p_off =
        ((uint32_t)(warp * 16 + (lane & 15)) * PLD + ((lane >> 4) << 3)) * 2;

    auto load_kv = [&](int kvi, int s) {
        const __half* gk = base + Cc + (size_t)(kvi * 64) * (3 * Cc);
        const __half* gv = base + 2 * Cc + (size_t)(kvi * 64) * (3 * Cc);
        const uint32_t dk = sb + (uint32_t)s * STG_H * 2;
        const uint32_t dv = dk + KS_H * 2;
#pragma unroll
        for (int it = 0; it < 2; it++) {
            int j = tid + it * 256;            // 512 chunks (64 rows x 8)
            int r = j >> 3, ch = j & 7;
            cpa16(dk + (uint32_t)(r * KLD + ch * 8) * 2,
                  gk + (size_t)r * (3 * Cc) + ch * 8);
        }
#pragma unroll
        for (int it = 0; it < 2; it++) {
            int j = tid + it * 256;
            int r = j >> 3, ch = j & 7;
            cpa16(dv + (uint32_t)(r * VLD + ch * 8) * 2,
                  gv + (size_t)r * (3 * Cc) + ch * 8);
        }
        CP_COMMIT();
    };

    // Q (128 rows) -> Ps (group 0), KV(0) -> stage 0 (group 1)
    {
        const __half* gq = base + (size_t)q0 * (3 * Cc);
#pragma unroll
        for (int it = 0; it < 4; it++) {
            int j = tid + it * 256;            // 1024 chunks (128 rows x 8)
            int r = j >> 3, ch = j & 7;
            cpa16(ps_base + (uint32_t)(r * PLD + ch * 8) * 2,
                  gq + (size_t)r * (3 * Cc) + ch * 8);
        }
        CP_COMMIT();
    }
    load_kv(0, 0);
    CP_WAIT(1);          // Q arrived
    __syncthreads();

    // Q fragments (A convention), 4 k16 chunks over d=64
    uint32_t qa[4][4];
#pragma unroll
    for (int kt = 0; kt < 4; kt++)
        LDSM4(qa[kt][0], qa[kt][1], qa[kt][2], qa[kt][3],
              ps_base + p_off + (uint32_t)(kt * 16) * 2);

    float oacc[8][4];
#pragma unroll
    for (int nt = 0; nt < 8; nt++)
#pragma unroll
        for (int q = 0; q < 4; q++) oacc[nt][q] = 0.0f;
    float m0 = -CUDART_INF_F, m1 = -CUDART_INF_F, l0 = 0.0f, l1 = 0.0f;

#pragma unroll 1
    for (int it = 0; it < Tt / 64; it++) {
        CP_WAIT(0);
        __syncthreads();
        if (it + 1 < Tt / 64) load_kv(it + 1, (it + 1) & 1);
        const uint32_t ks_base = sb + (uint32_t)(it & 1) * STG_H * 2;
        const uint32_t vs_base = ks_base + KS_H * 2;

        // S = Q @ K^T (16x64 per warp)
        float sacc[8][4];
#pragma unroll
        for (int nt = 0; nt < 8; nt++)
#pragma unroll
            for (int q = 0; q < 4; q++) sacc[nt][q] = 0.0f;
#pragma unroll
        for (int kt = 0; kt < 4; kt++) {
            const uint32_t kb = (uint32_t)(kt * 16) * 2;
#pragma unroll
            for (int j = 0; j < 4; j++) {
                uint32_t bq0, bq1, bq2, bq3;
                LDSM4(bq0, bq1, bq2, bq3,
                      ks_base + k_off + (uint32_t)j * 16 * KLD * 2 + kb);
                mma16(sacc[2 * j], qa[kt], bq0, bq2);
                mma16(sacc[2 * j + 1], qa[kt], bq1, bq3);
            }
        }
        // apply 1/sqrt(D) = 0.125
#pragma unroll
        for (int nt = 0; nt < 8; nt++)
#pragma unroll
            for (int q = 0; q < 4; q++) sacc[nt][q] *= 0.125f;

        // Online softmax in registers (rows g and g+8)
        float tm0 = -CUDART_INF_F, tm1 = -CUDART_INF_F;
#pragma unroll
        for (int nt = 0; nt < 8; nt++) {
            tm0 = fmaxf(tm0, fmaxf(sacc[nt][0], sacc[nt][1]));
            tm1 = fmaxf(tm1, fmaxf(sacc[nt][2], sacc[nt][3]));
        }
        tm0 = fmaxf(tm0, __shfl_xor_sync(0xffffffffu, tm0, 1));
        tm0 = fmaxf(tm0, __shfl_xor_sync(0xffffffffu, tm0, 2));
        tm1 = fmaxf(tm1, __shfl_xor_sync(0xffffffffu, tm1, 1));
        tm1 = fmaxf(tm1, __shfl_xor_sync(0xffffffffu, tm1, 2));
        const float mn0 = fmaxf(m0, tm0), mn1 = fmaxf(m1, tm1);
        const float f0 = __expf(m0 - mn0), f1 = __expf(m1 - mn1);
        float p0 = 0.0f, p1 = 0.0f;
#pragma unroll
        for (int nt = 0; nt < 8; nt++) {
            float e0 = __expf(sacc[nt][0] - mn0);
            float e1 = __expf(sacc[nt][1] - mn0);
            float e2 = __expf(sacc[nt][2] - mn1);
            float e3 = __expf(sacc[nt][3] - mn1);
            sacc[nt][0] = e0; sacc[nt][1] = e1;
            sacc[nt][2] = e2; sacc[nt][3] = e3;
            p0 += e0 + e1; p1 += e2 + e3;
        }
        p0 += __shfl_xor_sync(0xffffffffu, p0, 1);
        p0 += __shfl_xor_sync(0xffffffffu, p0, 2);
        p1 += __shfl_xor_sync(0xffffffffu, p1, 1);
        p1 += __shfl_xor_sync(0xffffffffu, p1, 2);
        l0 = l0 * f0 + p0; l1 = l1 * f1 + p1;
        m0 = mn0; m1 = mn1;
#pragma unroll
        for (int nt = 0; nt < 8; nt++) {
            oacc[nt][0] *= f0; oacc[nt][1] *= f0;
            oacc[nt][2] *= f1; oacc[nt][3] *= f1;
        }

        // P (fp16) -> per-warp smem rows, then PV
        __syncwarp();
        const int pr = warp * 16 + g;
#pragma unroll
        for (int nt = 0; nt < 8; nt++) {
            const int col = nt * 8 + 2 * tig;
            *(__half2*)(Ps + (size_t)pr * PLD + col) =
                __floats2half2_rn(sacc[nt][0], sacc[nt][1]);
            *(__half2*)(Ps + (size_t)(pr + 8) * PLD + col) =
                __floats2half2_rn(sacc[nt][2], sacc[nt][3]);
        }
        __syncwarp();

#pragma unroll
        for (int kt = 0; kt < 4; kt++) {       // k16 over kv-64
            uint32_t pa[4];
            LDSM4(pa[0], pa[1], pa[2], pa[3],
                  ps_base + p_off + (uint32_t)(kt * 16) * 2);
#pragma unroll
            for (int j = 0; j < 4; j++) {      // d16 groups
                uint32_t vq0, vq1, vq2, vq3;
                LDSM4T(vq0, vq1, vq2, vq3,
                       vs_base + v_off + (uint32_t)(kt * 16) * VLD * 2 +
                       (uint32_t)(j * 16) * 2);
                mma16(oacc[2 * j], pa, vq0, vq1);
                mma16(oacc[2 * j + 1], pa, vq2, vq3);
            }
        }
    }

    // Epilogue: O / l -> y (fp16)
    const float i0 = 1.0f / l0, i1 = 1.0f / l1;
    __half* yb = y + (size_t)b * Tt * Cc + (size_t)(q0 + warp * 16 + g) * Cc + h * Dd;
#pragma unroll
    for (int nt = 0; nt < 8; nt++) {
        const int col = nt * 8 + 2 * tig;
        *(__half2*)(yb + col) =
            __floats2half2_rn(oacc[nt][0] * i0, oacc[nt][1] * i0);
        *(__half2*)(yb + 8 * Cc + col) =
            __floats2half2_rn(oacc[nt][2] * i1, oacc[nt][3] * i1);
    }
}

// ---------------------------------------------------------------------------
extern "C" void kernel_launch(void* const* d_in, const int* in_sizes, int n_in,
                              void* d_out, int out_size)
{
    const float* x     = (const float*)d_in[0];
    const float* W_qkv = (const float*)d_in[3];
    const float* W_out = (const float*)d_in[4];
    float* out = (float*)d_out;

    __half *qkv, *y, *xh, *wq, *wo;
    cudaGetSymbolAddress((void**)&qkv, g_qkv);
    cudaGetSymbolAddress((void**)&y, g_y);
    cudaGetSymbolAddress((void**)&xh, g_xh);
    cudaGetSymbolAddress((void**)&wq, g_wq);
    cudaGetSymbolAddress((void**)&wo, g_wo);

    cudaFuncSetAttribute(gemm_nt_h<1>, cudaFuncAttributeMaxDynamicSharedMemorySize,
                         GSMEM);
    cudaFuncSetAttribute(gemm_nt_h<0>, cudaFuncAttributeMaxDynamicSharedMemorySize,
                         GSMEM);
    cudaFuncSetAttribute(flash_attn_h, cudaFuncAttributeMaxDynamicSharedMemorySize,
                         FL_SMEM);

    // 0) convert inputs to fp16 (single fused launch)
    {
        int n4x = Bb * Tt * Cc / 4, n4q = 3 * Cc * Cc / 4, n4o = Cc * Cc / 4;
        int tot = n4x + n4q + n4o;
        cvt_h3<<<(tot + 255) / 256, 256>>>(x, xh, n4x, W_qkv, wq, n4q,
                                           W_out, wo, n4o);
    }

    // 1) qkv = x @ W_qkv^T : [4096, 3072, 1024], fp16 out
    gemm_nt_h<1><<<dim3(3 * Cc / 128, Bb * Tt / 128), 256, GSMEM>>>(
        xh, wq, qkv, 3 * Cc, Cc);

    // 2) fused attention -> y [B, T, C] (fp16), 128-row Q tiles
    flash_attn_h<<<dim3(Tt / 128, Bb * Hh), 256, FL_SMEM>>>(qkv, y);

    // 3) out = y @ W_out^T : [4096, 1024, 1024], fp32 out
    gemm_nt_h<0><<<dim3(Cc / 128, Bb * Tt / 128), 256, GSMEM>>>(
        y, wo, out, Cc, Cc);
}

// round 13
// speedup vs baseline: 1.1114x; 1.1114x over previous
#include <cuda_runtime.h>
#include <cuda_fp16.h>
#include <cstdint>
#include <math_constants.h>

// Problem shape (fixed)
static constexpr int Bb = 2, Tt = 2048, Cc = 1024, Hh = 16, Dd = 64;

// Scratch (allocation-free device globals), all fp16 operands
__device__ __align__(256) __half g_qkv[(size_t)Bb * Tt * 3 * Cc];  // 25 MB
__device__ __align__(256) __half g_y[(size_t)Bb * Tt * Cc];        // 8 MB
__device__ __align__(256) __half g_xh[(size_t)Bb * Tt * Cc];       // 8 MB
__device__ __align__(256) __half g_wq[(size_t)3 * Cc * Cc];        // 6 MB
__device__ __align__(256) __half g_wo[(size_t)Cc * Cc];            // 2 MB

// ---------------------------------------------------------------------------
// Helpers
// ---------------------------------------------------------------------------
__device__ __forceinline__ uint32_t smem_u32(const void* p) {
    uint32_t a;
    asm("{ .reg .u64 t; cvta.to.shared.u64 t, %1; cvt.u32.u64 %0, t; }"
        : "=r"(a) : "l"(p));
    return a;
}
// mma.m16n8k16 fp16 -> fp32
__device__ __forceinline__ void mma16(float c[4], const uint32_t a[4],
                                      uint32_t b0, uint32_t b1) {
    asm volatile(
        "mma.sync.aligned.m16n8k16.row.col.f32.f16.f16.f32 "
        "{%0,%1,%2,%3}, {%4,%5,%6,%7}, {%8,%9}, {%0,%1,%2,%3};"
        : "+f"(c[0]), "+f"(c[1]), "+f"(c[2]), "+f"(c[3])
        : "r"(a[0]), "r"(a[1]), "r"(a[2]), "r"(a[3]), "r"(b0), "r"(b1));
}
__device__ __forceinline__ void cpa16(uint32_t dst, const void* src) {
    asm volatile("cp.async.cg.shared.global [%0], [%1], 16;"
                 :: "r"(dst), "l"(src));
}
__device__ __forceinline__ uint32_t packh2(float a, float b) {
    __half2 h = __floats2half2_rn(a, b);
    return *(uint32_t*)&h;
}
#define CP_COMMIT() asm volatile("cp.async.commit_group;" ::: "memory")
#define CP_WAIT(n)  asm volatile("cp.async.wait_group %0;" :: "n"(n) : "memory")
#define LDSM4(R0, R1, R2, R3, ADDR)                                          \
    asm volatile("ldmatrix.sync.aligned.m8n8.x4.shared.b16 {%0,%1,%2,%3}, [%4];" \
                 : "=r"(R0), "=r"(R1), "=r"(R2), "=r"(R3) : "r"(ADDR))
#define LDSM4T(R0, R1, R2, R3, ADDR)                                         \
    asm volatile("ldmatrix.sync.aligned.m8n8.x4.trans.shared.b16 {%0,%1,%2,%3}, [%4];" \
                 : "=r"(R0), "=r"(R1), "=r"(R2), "=r"(R3) : "r"(ADDR))

// ---------------------------------------------------------------------------
// Fused fp32 -> fp16 conversion of x, W_qkv, W_out (one launch)
// ---------------------------------------------------------------------------
__global__ void __launch_bounds__(256)
cvt_h3(const float* __restrict__ s0, __half* __restrict__ d0, int n0,
       const float* __restrict__ s1, __half* __restrict__ d1, int n1,
       const float* __restrict__ s2, __half* __restrict__ d2, int n2)
{
    int i = blockIdx.x * 256 + threadIdx.x;
    const float* s;
    __half* d;
    if (i < n0) { s = s0; d = d0; }
    else if (i < n0 + n1) { s = s1; d = d1; i -= n0; }
    else if (i < n0 + n1 + n2) { s = s2; d = d2; i -= n0 + n1; }
    else return;
    float4 v = ((const float4*)s)[i];
    ((__half2*)d)[2 * i]     = __floats2half2_rn(v.x, v.y);
    ((__half2*)d)[2 * i + 1] = __floats2half2_rn(v.z, v.w);
}

// ---------------------------------------------------------------------------
// fp16 GEMM: C[M,N] = A[M,K] @ B[N,K]^T (row-major, K contiguous, fp16 in)
// 128x128 block tile, K-chunks of 64 halves (128B rows). 256 threads,
// 8 warps 2x4, warp tile 64x32. 3-stage cp.async pipeline, 2 CTAs/SM.
// ---------------------------------------------------------------------------
static constexpr int GLD = 72;                  // smem row stride (halves)
static constexpr int GSTG_H = 2 * 128 * GLD;    // halves per stage (A+B)
static constexpr int GSMEM = 3 * GSTG_H * 2;    // 110592 bytes

template <int OUT_HALF>
__global__ void __launch_bounds__(256, 2)
gemm_nt_h(const __half* __restrict__ A, const __half* __restrict__ B,
          void* __restrict__ Cv, int N, int K)
{
    extern __shared__ char smc[];
    const uint32_t sb = smem_u32(smc);
    const int tid = threadIdx.x, warp = tid >> 5, lane = tid & 31;
    const int g = lane >> 2, tig = lane & 3;
    const int bm = blockIdx.y * 128, bn = blockIdx.x * 128;
    const int wm = (warp >> 2) * 64, wn = (warp & 3) * 32;

    // ldmatrix offsets (bytes): row = (lane&15), col-half = (lane>>4)*16B
    const uint32_t a_off =
        ((uint32_t)(wm + (lane & 15)) * GLD + ((lane >> 4) << 3)) * 2;
    const uint32_t b_off = (uint32_t)128 * GLD * 2 +
        ((uint32_t)(wn + (lane & 15)) * GLD + ((lane >> 4) << 3)) * 2;

    float acc[4][4][4];
#pragma unroll
    for (int mt = 0; mt < 4; mt++)
#pragma unroll
        for (int nt = 0; nt < 4; nt++)
#pragma unroll
            for (int q = 0; q < 4; q++) acc[mt][nt][q] = 0.0f;

    auto load_stage = [&](int c, int s) {
        const __half* ga = A + (size_t)bm * K + c * 64;
        const __half* gb = B + (size_t)bn * K + c * 64;
        const uint32_t da = sb + (uint32_t)s * GSTG_H * 2;
        const uint32_t db = da + 128 * GLD * 2;
#pragma unroll
        for (int it = 0; it < 4; it++) {
            int j = tid + it * 256;            // 1024 chunks (128 rows x 8)
            int r = j >> 3, ch = j & 7;
            cpa16(da + (uint32_t)(r * GLD + ch * 8) * 2,
                  ga + (size_t)r * K + ch * 8);
        }
#pragma unroll
        for (int it = 0; it < 4; it++) {
            int j = tid + it * 256;
            int r = j >> 3, ch = j & 7;
            cpa16(db + (uint32_t)(r * GLD + ch * 8) * 2,
                  gb + (size_t)r * K + ch * 8);
        }
        CP_COMMIT();
    };

    const int NCH = K / 64;
    load_stage(0, 0);
    load_stage(1, 1);
#pragma unroll 1
    for (int c = 0; c < NCH; c++) {
        if (c + 2 < NCH) { CP_WAIT(1); } else { CP_WAIT(0); }
        __syncthreads();
        if (c + 2 < NCH) load_stage(c + 2, (c + 2) % 3);
        const uint32_t stg = sb + (uint32_t)(c % 3) * GSTG_H * 2;
        const uint32_t aa = stg + a_off;
        const uint32_t ba = stg + b_off;
#pragma unroll
        for (int ks = 0; ks < 4; ks++) {       // k16 steps within 64
            const uint32_t kb = (uint32_t)(ks * 16) * 2;
            uint32_t af[4][4], bq[2][4];
#pragma unroll
            for (int mt = 0; mt < 4; mt++)
                LDSM4(af[mt][0], af[mt][1], af[mt][2], af[mt][3],
                      aa + (uint32_t)mt * 16 * GLD * 2 + kb);
#pragma unroll
            for (int j = 0; j < 2; j++)
                LDSM4(bq[j][0], bq[j][1], bq[j][2], bq[j][3],
                      ba + (uint32_t)j * 16 * GLD * 2 + kb);
#pragma unroll
            for (int mt = 0; mt < 4; mt++)
#pragma unroll
                for (int j = 0; j < 2; j++) {
                    mma16(acc[mt][2 * j], af[mt], bq[j][0], bq[j][2]);
                    mma16(acc[mt][2 * j + 1], af[mt], bq[j][1], bq[j][3]);
                }
        }
    }

    // Epilogue
#pragma unroll
    for (int mt = 0; mt < 4; mt++) {
        const int row = bm + wm + mt * 16 + g;
#pragma unroll
        for (int nt = 0; nt < 4; nt++) {
            const int col = bn + wn + nt * 8 + 2 * tig;
            if (OUT_HALF) {
                __half* C = (__half*)Cv;
                *(__half2*)(C + (size_t)row * N + col) =
                    __floats2half2_rn(acc[mt][nt][0], acc[mt][nt][1]);
                *(__half2*)(C + (size_t)(row + 8) * N + col) =
                    __floats2half2_rn(acc[mt][nt][2], acc[mt][nt][3]);
            } else {
                float* C = (float*)Cv;
                *(float2*)(C + (size_t)row * N + col) =
                    make_float2(acc[mt][nt][0], acc[mt][nt][1]);
                *(float2*)(C + (size_t)(row + 8) * N + col) =
                    make_float2(acc[mt][nt][2], acc[mt][nt][3]);
            }
        }
    }
}

// ---------------------------------------------------------------------------
// fp16 flash attention: 64 Q rows per CTA, 128 threads (R11 geometry).
// Register softmax/O. Q/K via ldmatrix, V via ldmatrix.trans.
// P fragments built DIRECTLY from S accumulator registers (fp16 layout
// identity: S C-frag == PV A-frag) — no P smem round trip.
// ---------------------------------------------------------------------------
static constexpr int KLD = 72, VLD = 72, PLD = 72;        // halves
static constexpr int KS_H = 64 * KLD;                     // 4608
static constexpr int VS_H = 64 * VLD;
static constexpr int STG_H = KS_H + VS_H;                 // 9216
static constexpr int PS_OFF_H = 2 * STG_H;                // 18432 (Q staging)
static constexpr int FL_SMEM = (PS_OFF_H + 64 * PLD) * 2; // 46080 bytes

__global__ void __launch_bounds__(128)
flash_attn_h(const __half* __restrict__ qkv, __half* __restrict__ y)
{
    extern __shared__ char smc[];
    const uint32_t sb = smem_u32(smc);
    const int tid = threadIdx.x, warp = tid >> 5, lane = tid & 31;
    const int g = lane >> 2, tig = lane & 3;
    const int q0 = blockIdx.x * 64;
    const int b = blockIdx.y >> 4, h = blockIdx.y & 15;
    const __half* base = qkv + (size_t)b * Tt * 3 * Cc + (size_t)h * Dd;
    const uint32_t ps_base = sb + (uint32_t)PS_OFF_H * 2;

    // ldmatrix offsets (bytes)
    const uint32_t k_off =
        ((uint32_t)(lane & 15) * KLD + ((lane >> 4) << 3)) * 2;
    const uint32_t v_off =
        ((uint32_t)((((lane >> 3) & 1) << 3) + (lane & 7)) * VLD +
         ((lane >> 4) << 3)) * 2;
    const uint32_t p_off =
        ((uint32_t)(warp * 16 + (lane & 15)) * PLD + ((lane >> 4) << 3)) * 2;

    auto load_kv = [&](int kvi, int s) {
        const __half* gk = base + Cc + (size_t)(kvi * 64) * (3 * Cc);
        const __half* gv = base + 2 * Cc + (size_t)(kvi * 64) * (3 * Cc);
        const uint32_t dk = sb + (uint32_t)s * STG_H * 2;
        const uint32_t dv = dk + KS_H * 2;
#pragma unroll
        for (int it = 0; it < 4; it++) {
            int j = tid + it * 128;            // 512 chunks (64 rows x 8)
            int r = j >> 3, ch = j & 7;
            cpa16(dk + (uint32_t)(r * KLD + ch * 8) * 2,
                  gk + (size_t)r * (3 * Cc) + ch * 8);
        }
#pragma unroll
        for (int it = 0; it < 4; it++) {
            int j = tid + it * 128;
            int r = j >> 3, ch = j & 7;
            cpa16(dv + (uint32_t)(r * VLD + ch * 8) * 2,
                  gv + (size_t)r * (3 * Cc) + ch * 8);
        }
        CP_COMMIT();
    };

    // Q -> staging (group 0), KV(0) -> stage 0 (group 1)
    {
        const __half* gq = base + (size_t)q0 * (3 * Cc);
#pragma unroll
        for (int it = 0; it < 4; it++) {
            int j = tid + it * 128;
            int r = j >> 3, ch = j & 7;
            cpa16(ps_base + (uint32_t)(r * PLD + ch * 8) * 2,
                  gq + (size_t)r * (3 * Cc) + ch * 8);
        }
        CP_COMMIT();
    }
    load_kv(0, 0);
    CP_WAIT(1);          // Q arrived
    __syncthreads();

    // Q fragments (A convention), 4 k16 chunks over d=64
    uint32_t qa[4][4];
#pragma unroll
    for (int kt = 0; kt < 4; kt++)
        LDSM4(qa[kt][0], qa[kt][1], qa[kt][2], qa[kt][3],
              ps_base + p_off + (uint32_t)(kt * 16) * 2);

    float oacc[8][4];
#pragma unroll
    for (int nt = 0; nt < 8; nt++)
#pragma unroll
        for (int q = 0; q < 4; q++) oacc[nt][q] = 0.0f;
    float m0 = -CUDART_INF_F, m1 = -CUDART_INF_F, l0 = 0.0f, l1 = 0.0f;

#pragma unroll 1
    for (int it = 0; it < Tt / 64; it++) {
        CP_WAIT(0);
        __syncthreads();
        if (it + 1 < Tt / 64) load_kv(it + 1, (it + 1) & 1);
        const uint32_t ks_base = sb + (uint32_t)(it & 1) * STG_H * 2;
        const uint32_t vs_base = ks_base + KS_H * 2;

        // S = Q @ K^T (16x64 per warp)
        float sacc[8][4];
#pragma unroll
        for (int nt = 0; nt < 8; nt++)
#pragma unroll
            for (int q = 0; q < 4; q++) sacc[nt][q] = 0.0f;
#pragma unroll
        for (int kt = 0; kt < 4; kt++) {
            const uint32_t kb = (uint32_t)(kt * 16) * 2;
#pragma unroll
            for (int j = 0; j < 4; j++) {
                uint32_t bq0, bq1, bq2, bq3;
                LDSM4(bq0, bq1, bq2, bq3,
                      ks_base + k_off + (uint32_t)j * 16 * KLD * 2 + kb);
                mma16(sacc[2 * j], qa[kt], bq0, bq2);
                mma16(sacc[2 * j + 1], qa[kt], bq1, bq3);
            }
        }
        // apply 1/sqrt(D) = 0.125
#pragma unroll
        for (int nt = 0; nt < 8; nt++)
#pragma unroll
            for (int q = 0; q < 4; q++) sacc[nt][q] *= 0.125f;

        // Online softmax in registers (rows g and g+8)
        float tm0 = -CUDART_INF_F, tm1 = -CUDART_INF_F;
#pragma unroll
        for (int nt = 0; nt < 8; nt++) {
            tm0 = fmaxf(tm0, fmaxf(sacc[nt][0], sacc[nt][1]));
            tm1 = fmaxf(tm1, fmaxf(sacc[nt][2], sacc[nt][3]));
        }
        tm0 = fmaxf(tm0, __shfl_xor_sync(0xffffffffu, tm0, 1));
        tm0 = fmaxf(tm0, __shfl_xor_sync(0xffffffffu, tm0, 2));
        tm1 = fmaxf(tm1, __shfl_xor_sync(0xffffffffu, tm1, 1));
        tm1 = fmaxf(tm1, __shfl_xor_sync(0xffffffffu, tm1, 2));
        const float mn0 = fmaxf(m0, tm0), mn1 = fmaxf(m1, tm1);
        const float f0 = __expf(m0 - mn0), f1 = __expf(m1 - mn1);
        float p0 = 0.0f, p1 = 0.0f;
#pragma unroll
        for (int nt = 0; nt < 8; nt++) {
            float e0 = __expf(sacc[nt][0] - mn0);
            float e1 = __expf(sacc[nt][1] - mn0);
            float e2 = __expf(sacc[nt][2] - mn1);
            float e3 = __expf(sacc[nt][3] - mn1);
            sacc[nt][0] = e0; sacc[nt][1] = e1;
            sacc[nt][2] = e2; sacc[nt][3] = e3;
            p0 += e0 + e1; p1 += e2 + e3;
        }
        p0 += __shfl_xor_sync(0xffffffffu, p0, 1);
        p0 += __shfl_xor_sync(0xffffffffu, p0, 2);
        p1 += __shfl_xor_sync(0xffffffffu, p1, 1);
        p1 += __shfl_xor_sync(0xffffffffu, p1, 2);
        l0 = l0 * f0 + p0; l1 = l1 * f1 + p1;
        m0 = mn0; m1 = mn1;
#pragma unroll
        for (int nt = 0; nt < 8; nt++) {
            oacc[nt][0] *= f0; oacc[nt][1] *= f0;
            oacc[nt][2] *= f1; oacc[nt][3] *= f1;
        }

        // PV: P fragments built directly from sacc registers (layout identity)
#pragma unroll
        for (int kt = 0; kt < 4; kt++) {       // k16 over kv-64
            uint32_t pa[4];
            pa[0] = packh2(sacc[2 * kt][0], sacc[2 * kt][1]);
            pa[1] = packh2(sacc[2 * kt][2], sacc[2 * kt][3]);
            pa[2] = packh2(sacc[2 * kt + 1][0], sacc[2 * kt + 1][1]);
            pa[3] = packh2(sacc[2 * kt + 1][2], sacc[2 * kt + 1][3]);
#pragma unroll
            for (int j = 0; j < 4; j++) {      // d16 groups
                uint32_t vq0, vq1, vq2, vq3;
                LDSM4T(vq0, vq1, vq2, vq3,
                       vs_base + v_off + (uint32_t)(kt * 16) * VLD * 2 +
                       (uint32_t)(j * 16) * 2);
                mma16(oacc[2 * j], pa, vq0, vq1);
                mma16(oacc[2 * j + 1], pa, vq2, vq3);
            }
        }
    }

    // Epilogue: O / l -> y (fp16)
    const float i0 = 1.0f / l0, i1 = 1.0f / l1;
    __half* yb = y + (size_t)b * Tt * Cc + (size_t)(q0 + warp * 16 + g) * Cc + h * Dd;
#pragma unroll
    for (int nt = 0; nt < 8; nt++) {
        const int col = nt * 8 + 2 * tig;
        *(__half2*)(yb + col) =
            __floats2half2_rn(oacc[nt][0] * i0, oacc[nt][1] * i0);
        *(__half2*)(yb + 8 * Cc + col) =
            __floats2half2_rn(oacc[nt][2] * i1, oacc[nt][3] * i1);
    }
}

// ---------------------------------------------------------------------------
extern "C" void kernel_launch(void* const* d_in, const int* in_sizes, int n_in,
                              void* d_out, int out_size)
{
    const float* x     = (const float*)d_in[0];
    const float* W_qkv = (const float*)d_in[3];
    const float* W_out = (const float*)d_in[4];
    float* out = (float*)d_out;

    __half *qkv, *y, *xh, *wq, *wo;
    cudaGetSymbolAddress((void**)&qkv, g_qkv);
    cudaGetSymbolAddress((void**)&y, g_y);
    cudaGetSymbolAddress((void**)&xh, g_xh);
    cudaGetSymbolAddress((void**)&wq, g_wq);
    cudaGetSymbolAddress((void**)&wo, g_wo);

    cudaFuncSetAttribute(gemm_nt_h<1>, cudaFuncAttributeMaxDynamicSharedMemorySize,
                         GSMEM);
    cudaFuncSetAttribute(gemm_nt_h<0>, cudaFuncAttributeMaxDynamicSharedMemorySize,
                         GSMEM);
    cudaFuncSetAttribute(flash_attn_h, cudaFuncAttributeMaxDynamicSharedMemorySize,
                         FL_SMEM);

    // 0) convert inputs to fp16 (single fused launch)
    {
        int n4x = Bb * Tt * Cc / 4, n4q = 3 * Cc * Cc / 4, n4o = Cc * Cc / 4;
        int tot = n4x + n4q + n4o;
        cvt_h3<<<(tot + 255) / 256, 256>>>(x, xh, n4x, W_qkv, wq, n4q,
                                           W_out, wo, n4o);
    }

    // 1) qkv = x @ W_qkv^T : [4096, 3072, 1024], fp16 out
    gemm_nt_h<1><<<dim3(3 * Cc / 128, Bb * Tt / 128), 256, GSMEM>>>(
        xh, wq, qkv, 3 * Cc, Cc);

    // 2) fused attention -> y [B, T, C] (fp16), 64-row Q tiles
    flash_attn_h<<<dim3(Tt / 64, Bb * Hh), 128, FL_SMEM>>>(qkv, y);

    // 3) out = y @ W_out^T : [4096, 1024, 1024], fp32 out
    gemm_nt_h<0><<<dim3(Cc / 128, Bb * Tt / 128), 256, GSMEM>>>(
        y, wo, out, Cc, Cc);
}

// round 14
// speedup vs baseline: 1.1145x; 1.0028x over previous
#include <cuda_runtime.h>
#include <cuda_fp16.h>
#include <cstdint>
#include <math_constants.h>

// Problem shape (fixed)
static constexpr int Bb = 2, Tt = 2048, Cc = 1024, Hh = 16, Dd = 64;

// Scratch (allocation-free device globals), all fp16 operands
__device__ __align__(256) __half g_qkv[(size_t)Bb * Tt * 3 * Cc];  // 25 MB
__device__ __align__(256) __half g_y[(size_t)Bb * Tt * Cc];        // 8 MB
__device__ __align__(256) __half g_xh[(size_t)Bb * Tt * Cc];       // 8 MB
__device__ __align__(256) __half g_wq[(size_t)3 * Cc * Cc];        // 6 MB
__device__ __align__(256) __half g_wo[(size_t)Cc * Cc];            // 2 MB

// ---------------------------------------------------------------------------
// Helpers
// ---------------------------------------------------------------------------
__device__ __forceinline__ uint32_t smem_u32(const void* p) {
    uint32_t a;
    asm("{ .reg .u64 t; cvta.to.shared.u64 t, %1; cvt.u32.u64 %0, t; }"
        : "=r"(a) : "l"(p));
    return a;
}
// mma.m16n8k16 fp16 -> fp32
__device__ __forceinline__ void mma16(float c[4], const uint32_t a[4],
                                      uint32_t b0, uint32_t b1) {
    asm volatile(
        "mma.sync.aligned.m16n8k16.row.col.f32.f16.f16.f32 "
        "{%0,%1,%2,%3}, {%4,%5,%6,%7}, {%8,%9}, {%0,%1,%2,%3};"
        : "+f"(c[0]), "+f"(c[1]), "+f"(c[2]), "+f"(c[3])
        : "r"(a[0]), "r"(a[1]), "r"(a[2]), "r"(a[3]), "r"(b0), "r"(b1));
}
__device__ __forceinline__ void cpa16(uint32_t dst, const void* src) {
    asm volatile("cp.async.cg.shared.global [%0], [%1], 16;"
                 :: "r"(dst), "l"(src));
}
__device__ __forceinline__ uint32_t packh2(float a, float b) {
    __half2 h = __floats2half2_rn(a, b);
    return *(uint32_t*)&h;
}
#define CP_COMMIT() asm volatile("cp.async.commit_group;" ::: "memory")
#define CP_WAIT(n)  asm volatile("cp.async.wait_group %0;" :: "n"(n) : "memory")
#define LDSM4(R0, R1, R2, R3, ADDR)                                          \
    asm volatile("ldmatrix.sync.aligned.m8n8.x4.shared.b16 {%0,%1,%2,%3}, [%4];" \
                 : "=r"(R0), "=r"(R1), "=r"(R2), "=r"(R3) : "r"(ADDR))
#define LDSM4T(R0, R1, R2, R3, ADDR)                                         \
    asm volatile("ldmatrix.sync.aligned.m8n8.x4.trans.shared.b16 {%0,%1,%2,%3}, [%4];" \
                 : "=r"(R0), "=r"(R1), "=r"(R2), "=r"(R3) : "r"(ADDR))

// ---------------------------------------------------------------------------
// Fused fp32 -> fp16 conversion of x, W_qkv, W_out (one launch)
// ---------------------------------------------------------------------------
__global__ void __launch_bounds__(256)
cvt_h3(const float* __restrict__ s0, __half* __restrict__ d0, int n0,
       const float* __restrict__ s1, __half* __restrict__ d1, int n1,
       const float* __restrict__ s2, __half* __restrict__ d2, int n2)
{
    int i = blockIdx.x * 256 + threadIdx.x;
    const float* s;
    __half* d;
    if (i < n0) { s = s0; d = d0; }
    else if (i < n0 + n1) { s = s1; d = d1; i -= n0; }
    else if (i < n0 + n1 + n2) { s = s2; d = d2; i -= n0 + n1; }
    else return;
    float4 v = ((const float4*)s)[i];
    ((__half2*)d)[2 * i]     = __floats2half2_rn(v.x, v.y);
    ((__half2*)d)[2 * i + 1] = __floats2half2_rn(v.z, v.w);
}

// ---------------------------------------------------------------------------
// fp16 GEMM: C[M,N] = A[M,K] @ B[N,K]^T (row-major, K contiguous, fp16 in)
// 128x128 block tile, K-chunks of 64 halves (128B rows). 256 threads,
// 8 warps 2x4, warp tile 64x32. 3-stage cp.async pipeline, 2 CTAs/SM.
// ---------------------------------------------------------------------------
static constexpr int GLD = 72;                  // smem row stride (halves)
static constexpr int GSTG_H = 2 * 128 * GLD;    // halves per stage (A+B)
static constexpr int GSMEM = 3 * GSTG_H * 2;    // 110592 bytes

template <int OUT_HALF>
__global__ void __launch_bounds__(256, 2)
gemm_nt_h(const __half* __restrict__ A, const __half* __restrict__ B,
          void* __restrict__ Cv, int N, int K)
{
    extern __shared__ char smc[];
    const uint32_t sb = smem_u32(smc);
    const int tid = threadIdx.x, warp = tid >> 5, lane = tid & 31;
    const int g = lane >> 2, tig = lane & 3;
    const int bm = blockIdx.y * 128, bn = blockIdx.x * 128;
    const int wm = (warp >> 2) * 64, wn = (warp & 3) * 32;

    // ldmatrix offsets (bytes): row = (lane&15), col-half = (lane>>4)*16B
    const uint32_t a_off =
        ((uint32_t)(wm + (lane & 15)) * GLD + ((lane >> 4) << 3)) * 2;
    const uint32_t b_off = (uint32_t)128 * GLD * 2 +
        ((uint32_t)(wn + (lane & 15)) * GLD + ((lane >> 4) << 3)) * 2;

    float acc[4][4][4];
#pragma unroll
    for (int mt = 0; mt < 4; mt++)
#pragma unroll
        for (int nt = 0; nt < 4; nt++)
#pragma unroll
            for (int q = 0; q < 4; q++) acc[mt][nt][q] = 0.0f;

    auto load_stage = [&](int c, int s) {
        const __half* ga = A + (size_t)bm * K + c * 64;
        const __half* gb = B + (size_t)bn * K + c * 64;
        const uint32_t da = sb + (uint32_t)s * GSTG_H * 2;
        const uint32_t db = da + 128 * GLD * 2;
#pragma unroll
        for (int it = 0; it < 4; it++) {
            int j = tid + it * 256;            // 1024 chunks (128 rows x 8)
            int r = j >> 3, ch = j & 7;
            cpa16(da + (uint32_t)(r * GLD + ch * 8) * 2,
                  ga + (size_t)r * K + ch * 8);
        }
#pragma unroll
        for (int it = 0; it < 4; it++) {
            int j = tid + it * 256;
            int r = j >> 3, ch = j & 7;
            cpa16(db + (uint32_t)(r * GLD + ch * 8) * 2,
                  gb + (size_t)r * K + ch * 8);
        }
        CP_COMMIT();
    };

    const int NCH = K / 64;
    load_stage(0, 0);
    load_stage(1, 1);
#pragma unroll 1
    for (int c = 0; c < NCH; c++) {
        if (c + 2 < NCH) { CP_WAIT(1); } else { CP_WAIT(0); }
        __syncthreads();
        if (c + 2 < NCH) load_stage(c + 2, (c + 2) % 3);
        const uint32_t stg = sb + (uint32_t)(c % 3) * GSTG_H * 2;
        const uint32_t aa = stg + a_off;
        const uint32_t ba = stg + b_off;
#pragma unroll
        for (int ks = 0; ks < 4; ks++) {       // k16 steps within 64
            const uint32_t kb = (uint32_t)(ks * 16) * 2;
            uint32_t af[4][4], bq[2][4];
#pragma unroll
            for (int mt = 0; mt < 4; mt++)
                LDSM4(af[mt][0], af[mt][1], af[mt][2], af[mt][3],
                      aa + (uint32_t)mt * 16 * GLD * 2 + kb);
#pragma unroll
            for (int j = 0; j < 2; j++)
                LDSM4(bq[j][0], bq[j][1], bq[j][2], bq[j][3],
                      ba + (uint32_t)j * 16 * GLD * 2 + kb);
#pragma unroll
            for (int mt = 0; mt < 4; mt++)
#pragma unroll
                for (int j = 0; j < 2; j++) {
                    mma16(acc[mt][2 * j], af[mt], bq[j][0], bq[j][2]);
                    mma16(acc[mt][2 * j + 1], af[mt], bq[j][1], bq[j][3]);
                }
        }
    }

    // Epilogue
#pragma unroll
    for (int mt = 0; mt < 4; mt++) {
        const int row = bm + wm + mt * 16 + g;
#pragma unroll
        for (int nt = 0; nt < 4; nt++) {
            const int col = bn + wn + nt * 8 + 2 * tig;
            if (OUT_HALF) {
                __half* C = (__half*)Cv;
                *(__half2*)(C + (size_t)row * N + col) =
                    __floats2half2_rn(acc[mt][nt][0], acc[mt][nt][1]);
                *(__half2*)(C + (size_t)(row + 8) * N + col) =
                    __floats2half2_rn(acc[mt][nt][2], acc[mt][nt][3]);
            } else {
                float* C = (float*)Cv;
                *(float2*)(C + (size_t)row * N + col) =
                    make_float2(acc[mt][nt][0], acc[mt][nt][1]);
                *(float2*)(C + (size_t)(row + 8) * N + col) =
                    make_float2(acc[mt][nt][2], acc[mt][nt][3]);
            }
        }
    }
}

// ---------------------------------------------------------------------------
// fp16 flash attention: 64 Q rows per CTA, 128 threads (R11 geometry).
// Register softmax/O. Q/K via ldmatrix, V via ldmatrix.trans.
// P fragments built DIRECTLY from S accumulator registers (fp16 layout
// identity: S C-frag == PV A-frag) — no P smem round trip.
// ---------------------------------------------------------------------------
static constexpr int KLD = 72, VLD = 72, PLD = 72;        // halves
static constexpr int KS_H = 64 * KLD;                     // 4608
static constexpr int VS_H = 64 * VLD;
static constexpr int STG_H = KS_H + VS_H;                 // 9216
static constexpr int PS_OFF_H = 2 * STG_H;                // 18432 (Q staging)
static constexpr int FL_SMEM = (PS_OFF_H + 64 * PLD) * 2; // 46080 bytes

__global__ void __launch_bounds__(128)
flash_attn_h(const __half* __restrict__ qkv, __half* __restrict__ y)
{
    extern __shared__ char smc[];
    const uint32_t sb = smem_u32(smc);
    const int tid = threadIdx.x, warp = tid >> 5, lane = tid & 31;
    const int g = lane >> 2, tig = lane & 3;
    const int q0 = blockIdx.x * 64;
    const int b = blockIdx.y >> 4, h = blockIdx.y & 15;
    const __half* base = qkv + (size_t)b * Tt * 3 * Cc + (size_t)h * Dd;
    const uint32_t ps_base = sb + (uint32_t)PS_OFF_H * 2;

    // ldmatrix offsets (bytes)
    const uint32_t k_off =
        ((uint32_t)(lane & 15) * KLD + ((lane >> 4) << 3)) * 2;
    const uint32_t v_off =
        ((uint32_t)((((lane >> 3) & 1) << 3) + (lane & 7)) * VLD +
         ((lane >> 4) << 3)) * 2;
    const uint32_t p_off =
        ((uint32_t)(warp * 16 + (lane & 15)) * PLD + ((lane >> 4) << 3)) * 2;

    auto load_kv = [&](int kvi, int s) {
        const __half* gk = base + Cc + (size_t)(kvi * 64) * (3 * Cc);
        const __half* gv = base + 2 * Cc + (size_t)(kvi * 64) * (3 * Cc);
        const uint32_t dk = sb + (uint32_t)s * STG_H * 2;
        const uint32_t dv = dk + KS_H * 2;
#pragma unroll
        for (int it = 0; it < 4; it++) {
            int j = tid + it * 128;            // 512 chunks (64 rows x 8)
            int r = j >> 3, ch = j & 7;
            cpa16(dk + (uint32_t)(r * KLD + ch * 8) * 2,
                  gk + (size_t)r * (3 * Cc) + ch * 8);
        }
#pragma unroll
        for (int it = 0; it < 4; it++) {
            int j = tid + it * 128;
            int r = j >> 3, ch = j & 7;
            cpa16(dv + (uint32_t)(r * VLD + ch * 8) * 2,
                  gv + (size_t)r * (3 * Cc) + ch * 8);
        }
        CP_COMMIT();
    };

    // Q -> staging (group 0), KV(0) -> stage 0 (group 1)
    {
        const __half* gq = base + (size_t)q0 * (3 * Cc);
#pragma unroll
        for (int it = 0; it < 4; it++) {
            int j = tid + it * 128;
            int r = j >> 3, ch = j & 7;
            cpa16(ps_base + (uint32_t)(r * PLD + ch * 8) * 2,
                  gq + (size_t)r * (3 * Cc) + ch * 8);
        }
        CP_COMMIT();
    }
    load_kv(0, 0);
    CP_WAIT(1);          // Q arrived
    __syncthreads();

    // Q fragments (A convention), 4 k16 chunks over d=64
    uint32_t qa[4][4];
#pragma unroll
    for (int kt = 0; kt < 4; kt++)
        LDSM4(qa[kt][0], qa[kt][1], qa[kt][2], qa[kt][3],
              ps_base + p_off + (uint32_t)(kt * 16) * 2);

    float oacc[8][4];
#pragma unroll
    for (int nt = 0; nt < 8; nt++)
#pragma unroll
        for (int q = 0; q < 4; q++) oacc[nt][q] = 0.0f;
    float m0 = -CUDART_INF_F, m1 = -CUDART_INF_F, l0 = 0.0f, l1 = 0.0f;

#pragma unroll 1
    for (int it = 0; it < Tt / 64; it++) {
        CP_WAIT(0);
        __syncthreads();
        if (it + 1 < Tt / 64) load_kv(it + 1, (it + 1) & 1);
        const uint32_t ks_base = sb + (uint32_t)(it & 1) * STG_H * 2;
        const uint32_t vs_base = ks_base + KS_H * 2;

        // S = Q @ K^T (16x64 per warp)
        float sacc[8][4];
#pragma unroll
        for (int nt = 0; nt < 8; nt++)
#pragma unroll
            for (int q = 0; q < 4; q++) sacc[nt][q] = 0.0f;
#pragma unroll
        for (int kt = 0; kt < 4; kt++) {
            const uint32_t kb = (uint32_t)(kt * 16) * 2;
#pragma unroll
            for (int j = 0; j < 4; j++) {
                uint32_t bq0, bq1, bq2, bq3;
                LDSM4(bq0, bq1, bq2, bq3,
                      ks_base + k_off + (uint32_t)j * 16 * KLD * 2 + kb);
                mma16(sacc[2 * j], qa[kt], bq0, bq2);
                mma16(sacc[2 * j + 1], qa[kt], bq1, bq3);
            }
        }
        // apply 1/sqrt(D) = 0.125
#pragma unroll
        for (int nt = 0; nt < 8; nt++)
#pragma unroll
            for (int q = 0; q < 4; q++) sacc[nt][q] *= 0.125f;

        // Online softmax in registers (rows g and g+8)
        float tm0 = -CUDART_INF_F, tm1 = -CUDART_INF_F;
#pragma unroll
        for (int nt = 0; nt < 8; nt++) {
            tm0 = fmaxf(tm0, fmaxf(sacc[nt][0], sacc[nt][1]));
            tm1 = fmaxf(tm1, fmaxf(sacc[nt][2], sacc[nt][3]));
        }
        tm0 = fmaxf(tm0, __shfl_xor_sync(0xffffffffu, tm0, 1));
        tm0 = fmaxf(tm0, __shfl_xor_sync(0xffffffffu, tm0, 2));
        tm1 = fmaxf(tm1, __shfl_xor_sync(0xffffffffu, tm1, 1));
        tm1 = fmaxf(tm1, __shfl_xor_sync(0xffffffffu, tm1, 2));
        const float mn0 = fmaxf(m0, tm0), mn1 = fmaxf(m1, tm1);
        const float f0 = __expf(m0 - mn0), f1 = __expf(m1 - mn1);
        float p0 = 0.0f, p1 = 0.0f;
#pragma unroll
        for (int nt = 0; nt < 8; nt++) {
            float e0 = __expf(sacc[nt][0] - mn0);
            float e1 = __expf(sacc[nt][1] - mn0);
            float e2 = __expf(sacc[nt][2] - mn1);
            float e3 = __expf(sacc[nt][3] - mn1);
            sacc[nt][0] = e0; sacc[nt][1] = e1;
            sacc[nt][2] = e2; sacc[nt][3] = e3;
            p0 += e0 + e1; p1 += e2 + e3;
        }
        p0 += __shfl_xor_sync(0xffffffffu, p0, 1);
        p0 += __shfl_xor_sync(0xffffffffu, p0, 2);
        p1 += __shfl_xor_sync(0xffffffffu, p1, 1);
        p1 += __shfl_xor_sync(0xffffffffu, p1, 2);
        l0 = l0 * f0 + p0; l1 = l1 * f1 + p1;
        m0 = mn0; m1 = mn1;
#pragma unroll
        for (int nt = 0; nt < 8; nt++) {
            oacc[nt][0] *= f0; oacc[nt][1] *= f0;
            oacc[nt][2] *= f1; oacc[nt][3] *= f1;
        }

        // PV: P fragments built directly from sacc registers (layout identity)
#pragma unroll
        for (int kt = 0; kt < 4; kt++) {       // k16 over kv-64
            uint32_t pa[4];
            pa[0] = packh2(sacc[2 * kt][0], sacc[2 * kt][1]);
            pa[1] = packh2(sacc[2 * kt][2], sacc[2 * kt][3]);
            pa[2] = packh2(sacc[2 * kt + 1][0], sacc[2 * kt + 1][1]);
            pa[3] = packh2(sacc[2 * kt + 1][2], sacc[2 * kt + 1][3]);
#pragma unroll
            for (int j = 0; j < 4; j++) {      // d16 groups
                uint32_t vq0, vq1, vq2, vq3;
                LDSM4T(vq0, vq1, vq2, vq3,
                       vs_base + v_off + (uint32_t)(kt * 16) * VLD * 2 +
                       (uint32_t)(j * 16) * 2);
                mma16(oacc[2 * j], pa, vq0, vq1);
                mma16(oacc[2 * j + 1], pa, vq2, vq3);
            }
        }
    }

    // Epilogue: O / l -> y (fp16)
    const float i0 = 1.0f / l0, i1 = 1.0f / l1;
    __half* yb = y + (size_t)b * Tt * Cc + (size_t)(q0 + warp * 16 + g) * Cc + h * Dd;
#pragma unroll
    for (int nt = 0; nt < 8; nt++) {
        const int col = nt * 8 + 2 * tig;
        *(__half2*)(yb + col) =
            __floats2half2_rn(oacc[nt][0] * i0, oacc[nt][1] * i0);
        *(__half2*)(yb + 8 * Cc + col) =
            __floats2half2_rn(oacc[nt][2] * i1, oacc[nt][3] * i1);
    }
}

// ---------------------------------------------------------------------------
extern "C" void kernel_launch(void* const* d_in, const int* in_sizes, int n_in,
                              void* d_out, int out_size)
{
    const float* x     = (const float*)d_in[0];
    const float* W_qkv = (const float*)d_in[3];
    const float* W_out = (const float*)d_in[4];
    float* out = (float*)d_out;

    __half *qkv, *y, *xh, *wq, *wo;
    cudaGetSymbolAddress((void**)&qkv, g_qkv);
    cudaGetSymbolAddress((void**)&y, g_y);
    cudaGetSymbolAddress((void**)&xh, g_xh);
    cudaGetSymbolAddress((void**)&wq, g_wq);
    cudaGetSymbolAddress((void**)&wo, g_wo);

    cudaFuncSetAttribute(gemm_nt_h<1>, cudaFuncAttributeMaxDynamicSharedMemorySize,
                         GSMEM);
    cudaFuncSetAttribute(gemm_nt_h<0>, cudaFuncAttributeMaxDynamicSharedMemorySize,
                         GSMEM);
    cudaFuncSetAttribute(flash_attn_h, cudaFuncAttributeMaxDynamicSharedMemorySize,
                         FL_SMEM);

    // 0) convert inputs to fp16 (single fused launch)
    {
        int n4x = Bb * Tt * Cc / 4, n4q = 3 * Cc * Cc / 4, n4o = Cc * Cc / 4;
        int tot = n4x + n4q + n4o;
        cvt_h3<<<(tot + 255) / 256, 256>>>(x, xh, n4x, W_qkv, wq, n4q,
                                           W_out, wo, n4o);
    }

    // 1) qkv = x @ W_qkv^T : [4096, 3072, 1024], fp16 out
    gemm_nt_h<1><<<dim3(3 * Cc / 128, Bb * Tt / 128), 256, GSMEM>>>(
        xh, wq, qkv, 3 * Cc, Cc);

    // 2) fused attention -> y [B, T, C] (fp16), 64-row Q tiles
    flash_attn_h<<<dim3(Tt / 64, Bb * Hh), 128, FL_SMEM>>>(qkv, y);

    // 3) out = y @ W_out^T : [4096, 1024, 1024], fp32 out
    gemm_nt_h<0><<<dim3(Cc / 128, Bb * Tt / 128), 256, GSMEM>>>(
        y, wo, out, Cc, Cc);
}